// round 3
// baseline (speedup 1.0000x reference)
#include <cuda_runtime.h>
#include <cstdint>

#define D 64
#define MAXN 150001
#define MAXNNZ 2000000
#define SCAN_B 256
#define MAXBLKS ((MAXN + SCAN_B - 1) / SCAN_B)

// ---- scratch (__device__ globals; no allocation allowed) ----
__device__ __align__(16) float g_f1[(size_t)MAXN * D];
__device__ __align__(16) float2 g_edges[MAXNNZ];   // {col_bits, val}, bucketed by row
__device__ int g_counts[MAXN];
__device__ int g_offs[MAXN + 1];
__device__ int g_cursor[MAXN];
__device__ unsigned long long g_desc[MAXBLKS];
__device__ unsigned int g_ticket;

// ---- histogram: 4 edges per thread ----
__global__ void hist_kernel(const int* __restrict__ rows, int nnz, int* __restrict__ counts) {
    int t = blockIdx.x * blockDim.x + threadIdx.x;
    int base = t * 4;
    if (base + 4 <= nnz) {
        int4 r = *(const int4*)(rows + base);
        atomicAdd(&counts[r.x], 1);
        atomicAdd(&counts[r.y], 1);
        atomicAdd(&counts[r.z], 1);
        atomicAdd(&counts[r.w], 1);
    } else {
        for (int k = base; k < nnz; k++) atomicAdd(&counts[rows[k]], 1);
    }
}

// ---- single-pass decoupled-lookback exclusive scan -> offs + cursor ----
__global__ void scan_kernel(const int* __restrict__ counts, int n,
                            int* __restrict__ offs, int* __restrict__ cursor,
                            unsigned long long* __restrict__ desc,
                            unsigned int* __restrict__ ticket) {
    __shared__ int s_warp[8];
    __shared__ int s_bid;
    __shared__ int s_excl;
    int lane = threadIdx.x & 31;
    int wid = threadIdx.x >> 5;
    if (threadIdx.x == 0) s_bid = (int)atomicAdd(ticket, 1u);
    __syncthreads();
    int bid = s_bid;
    int i = bid * SCAN_B + threadIdx.x;
    int v = (i < n) ? counts[i] : 0;
    // warp inclusive scan
    int x = v;
    #pragma unroll
    for (int o = 1; o < 32; o <<= 1) {
        int t = __shfl_up_sync(0xffffffffu, x, o);
        if (lane >= o) x += t;
    }
    if (lane == 31) s_warp[wid] = x;
    __syncthreads();
    if (wid == 0 && lane < 8) {
        int w = s_warp[lane];
        #pragma unroll
        for (int o = 1; o < 8; o <<= 1) {
            int t = __shfl_up_sync(0xffu, w, o);
            if (lane >= o) w += t;
        }
        s_warp[lane] = w;
    }
    __syncthreads();
    int incl = x + (wid ? s_warp[wid - 1] : 0);
    int total = s_warp[7];
    if (threadIdx.x == 0) {
        if (bid == 0) {
            atomicExch(&desc[0], (2ULL << 62) | (unsigned long long)(unsigned)total);
            s_excl = 0;
        } else {
            atomicExch(&desc[bid], (1ULL << 62) | (unsigned long long)(unsigned)total);
            int excl = 0;
            int j = bid - 1;
            while (true) {
                unsigned long long d;
                do { d = atomicAdd(&desc[j], 0ULL); } while ((d >> 62) == 0ULL);
                excl += (int)(unsigned)d;
                if ((d >> 62) == 2ULL) break;
                j--;
            }
            s_excl = excl;
            atomicExch(&desc[bid], (2ULL << 62) | (unsigned long long)(unsigned)(excl + total));
        }
    }
    __syncthreads();
    int excl = s_excl;
    if (i < n) {
        int inc = incl + excl;
        offs[i + 1] = inc;
        cursor[i] = inc - v;
        if (i == 0) offs[0] = 0;
    }
}

// ---- bucket edges by row: 4 edges per thread ----
__global__ void bucket_kernel(const int* __restrict__ rows, const int* __restrict__ cols,
                              const float* __restrict__ vals, int nnz,
                              int* __restrict__ cursor, float2* __restrict__ edges) {
    int t = blockIdx.x * blockDim.x + threadIdx.x;
    int base = t * 4;
    if (base + 4 <= nnz) {
        int4 r = *(const int4*)(rows + base);
        int4 c = *(const int4*)(cols + base);
        float4 v = *(const float4*)(vals + base);
        int p0 = atomicAdd(&cursor[r.x], 1);
        int p1 = atomicAdd(&cursor[r.y], 1);
        int p2 = atomicAdd(&cursor[r.z], 1);
        int p3 = atomicAdd(&cursor[r.w], 1);
        edges[p0] = make_float2(__int_as_float(c.x), v.x);
        edges[p1] = make_float2(__int_as_float(c.y), v.y);
        edges[p2] = make_float2(__int_as_float(c.z), v.z);
        edges[p3] = make_float2(__int_as_float(c.w), v.w);
    } else {
        for (int k = base; k < nnz; k++) {
            int pos = atomicAdd(&cursor[rows[k]], 1);
            edges[pos] = make_float2(__int_as_float(cols[k]), vals[k]);
        }
    }
}

// ---- fused gather-SpMM + L2-normalize + output ----
// FIRST=true : gather from concat(A,B) by branch; writes f1; out = feat/3 + norm(f)/3
// FIRST=false: gather from fin(=f1); no fnext write; out += norm(f)/3
template <bool FIRST>
__global__ void spmm_kernel(const float2* __restrict__ edges, const int* __restrict__ offs,
                            const float* __restrict__ A, const float* __restrict__ B,
                            const float* __restrict__ fin, float* __restrict__ fnext,
                            int nA, int n,
                            float* __restrict__ outA, float* __restrict__ outB) {
    int row = (int)((blockIdx.x * blockDim.x + threadIdx.x) >> 5);
    int lane = threadIdx.x & 31;
    if (row >= n) return;
    int s = offs[row], e = offs[row + 1];
    int l2 = lane * 2;
    float ax = 0.f, ay = 0.f;
    int i = s;
    for (; i + 4 <= e; i += 4) {
        float2 h0 = edges[i];
        float2 h1 = edges[i + 1];
        float2 h2 = edges[i + 2];
        float2 h3 = edges[i + 3];
        int c0 = __float_as_int(h0.x), c1 = __float_as_int(h1.x);
        int c2 = __float_as_int(h2.x), c3 = __float_as_int(h3.x);
        const float *p0, *p1, *p2, *p3;
        if (FIRST) {
            p0 = (c0 < nA) ? (A + (size_t)c0 * D) : (B + (size_t)(c0 - nA) * D);
            p1 = (c1 < nA) ? (A + (size_t)c1 * D) : (B + (size_t)(c1 - nA) * D);
            p2 = (c2 < nA) ? (A + (size_t)c2 * D) : (B + (size_t)(c2 - nA) * D);
            p3 = (c3 < nA) ? (A + (size_t)c3 * D) : (B + (size_t)(c3 - nA) * D);
        } else {
            p0 = fin + (size_t)c0 * D;
            p1 = fin + (size_t)c1 * D;
            p2 = fin + (size_t)c2 * D;
            p3 = fin + (size_t)c3 * D;
        }
        float2 x0 = *(const float2*)(p0 + l2);
        float2 x1 = *(const float2*)(p1 + l2);
        float2 x2 = *(const float2*)(p2 + l2);
        float2 x3 = *(const float2*)(p3 + l2);
        ax += h0.y * x0.x + h1.y * x1.x + h2.y * x2.x + h3.y * x3.x;
        ay += h0.y * x0.y + h1.y * x1.y + h2.y * x2.y + h3.y * x3.y;
    }
    for (; i < e; i++) {
        float2 h = edges[i];
        int c = __float_as_int(h.x);
        const float* p;
        if (FIRST) p = (c < nA) ? (A + (size_t)c * D) : (B + (size_t)(c - nA) * D);
        else       p = fin + (size_t)c * D;
        float2 x = *(const float2*)(p + l2);
        ax += h.y * x.x;
        ay += h.y * x.y;
    }
    if (FIRST)
        *(float2*)(fnext + (size_t)row * D + l2) = make_float2(ax, ay);
    float ssum = ax * ax + ay * ay;
    #pragma unroll
    for (int o = 16; o; o >>= 1) ssum += __shfl_xor_sync(0xffffffffu, ssum, o);
    const float k = 1.0f / 3.0f;
    float scale = k / fmaxf(sqrtf(ssum), 1e-12f);
    float* dst = (row < nA) ? (outA + (size_t)row * D) : (outB + (size_t)(row - nA) * D);
    float2* d2 = (float2*)dst + lane;
    if (FIRST) {
        const float* own = (row < nA) ? (A + (size_t)row * D) : (B + (size_t)(row - nA) * D);
        float2 f = *(const float2*)(own + l2);
        *d2 = make_float2(f.x * k + ax * scale, f.y * k + ay * scale);
    } else {
        float2 o2 = *d2;
        o2.x += ax * scale;
        o2.y += ay * scale;
        *d2 = o2;
    }
}

static void run_prop(const int* rows, const int* cols, const float* vals, int nnz,
                     const float* A, const float* B, int nA, int nB,
                     float* outA, float* outB,
                     float* f1, float2* edges,
                     int* counts, int* offs, int* cursor,
                     unsigned long long* desc, unsigned int* ticket) {
    int n = nA + nB;
    int nb = (n + SCAN_B - 1) / SCAN_B;

    cudaMemsetAsync(counts, 0, (size_t)n * sizeof(int), 0);
    cudaMemsetAsync(desc, 0, (size_t)nb * sizeof(unsigned long long), 0);
    cudaMemsetAsync(ticket, 0, sizeof(unsigned int), 0);

    int eth = (nnz + 3) / 4;   // 4 edges/thread
    hist_kernel<<<(eth + 255) / 256, 256>>>(rows, nnz, counts);
    scan_kernel<<<nb, SCAN_B>>>(counts, n, offs, cursor, desc, ticket);
    bucket_kernel<<<(eth + 255) / 256, 256>>>(rows, cols, vals, nnz, cursor, edges);

    int blocks = (n + 7) / 8;   // 8 warps/block
    spmm_kernel<true><<<blocks, 256>>>(edges, offs, A, B, nullptr, f1, nA, n, outA, outB);
    spmm_kernel<false><<<blocks, 256>>>(edges, offs, A, B, f1, nullptr, nA, n, outA, outB);
}

extern "C" void kernel_launch(void* const* d_in, const int* in_sizes, int n_in,
                              void* d_out, int out_size) {
    const float* users_feature   = (const float*)d_in[0];
    const float* items_feature   = (const float*)d_in[1];
    const float* bundles_feature = (const float*)d_in[2];
    const float* ui_vals = (const float*)d_in[3];
    const float* bi_vals = (const float*)d_in[4];
    const float* ub_vals = (const float*)d_in[5];
    const int* ui_rows = (const int*)d_in[6];
    const int* ui_cols = (const int*)d_in[7];
    const int* bi_rows = (const int*)d_in[8];
    const int* bi_cols = (const int*)d_in[9];
    const int* ub_rows = (const int*)d_in[10];
    const int* ub_cols = (const int*)d_in[11];

    int U  = in_sizes[0] / D;
    int NI = in_sizes[1] / D;
    int NB = in_sizes[2] / D;
    int nnz_ui = in_sizes[3];
    int nnz_bi = in_sizes[4];
    int nnz_ub = in_sizes[5];

    float* out = (float*)d_out;

    float* f1;
    float2* edges;
    int *counts, *offs, *cursor;
    unsigned long long* desc;
    unsigned int* ticket;
    cudaGetSymbolAddress((void**)&f1, g_f1);
    cudaGetSymbolAddress((void**)&edges, g_edges);
    cudaGetSymbolAddress((void**)&counts, g_counts);
    cudaGetSymbolAddress((void**)&offs, g_offs);
    cudaGetSymbolAddress((void**)&cursor, g_cursor);
    cudaGetSymbolAddress((void**)&desc, g_desc);
    cudaGetSymbolAddress((void**)&ticket, g_ticket);

    // Output layout: [UI_u(U), UB_u(U), BI_b(NB), UB_b(NB), UI_i(NI), BI_i(NI)]
    float* o_ui_u = out;
    float* o_ub_u = out + (size_t)U * D;
    float* o_bi_b = out + (size_t)2 * U * D;
    float* o_ub_b = out + ((size_t)2 * U + NB) * D;
    float* o_ui_i = out + ((size_t)2 * U + 2 * NB) * D;
    float* o_bi_i = out + ((size_t)2 * U + 2 * NB + NI) * D;

    run_prop(ui_rows, ui_cols, ui_vals, nnz_ui, users_feature, items_feature,
             U, NI, o_ui_u, o_ui_i, f1, edges, counts, offs, cursor, desc, ticket);
    run_prop(bi_rows, bi_cols, bi_vals, nnz_bi, bundles_feature, items_feature,
             NB, NI, o_bi_b, o_bi_i, f1, edges, counts, offs, cursor, desc, ticket);
    run_prop(ub_rows, ub_cols, ub_vals, nnz_ub, users_feature, bundles_feature,
             U, NB, o_ub_u, o_ub_b, f1, edges, counts, offs, cursor, desc, ticket);
}

// round 4
// speedup vs baseline: 1.0214x; 1.0214x over previous
#include <cuda_runtime.h>
#include <cstdint>

#define D 64
#define MAXNTOT 340002           // 150000 + 70000 + 120000 (+pad)
#define MAXNNZALL 4000008        // 2M + 1M + 1M (+pad)
#define SCAN_B 256
#define MAXBLKS ((MAXNTOT + SCAN_B - 1) / SCAN_B)

// ---- scratch (__device__ globals; no allocation allowed) ----
__device__ __align__(16) float g_f0[(size_t)MAXNTOT * D];   // ~87 MB
__device__ __align__(16) float g_f1[(size_t)MAXNTOT * D];   // ~87 MB
__device__ __align__(16) float2 g_edges[MAXNNZALL];         // {global col bits, val}
__device__ int g_counts[MAXNTOT];
__device__ int g_offs[MAXNTOT + 1];
__device__ int g_cursor[MAXNTOT];
__device__ unsigned long long g_desc[MAXBLKS];
__device__ unsigned int g_ticket;

// ---- init: f0 = concat of all three propagation inputs (global row space) ----
__global__ void init_kernel(const float* __restrict__ Uf, const float* __restrict__ If,
                            const float* __restrict__ Bf,
                            int U, int NB, int R1, int R2, int ntot,
                            float* __restrict__ f0) {
    int idx = blockIdx.x * blockDim.x + threadIdx.x;   // one float4 per thread
    if (idx >= ntot * (D / 4)) return;
    int row = idx >> 4;
    int c = (idx & 15) * 4;
    const float* src;
    if (row < R1) {                         // UI: users | items
        src = (row < U) ? (Uf + (size_t)row * D) : (If + (size_t)(row - U) * D);
    } else if (row < R2) {                  // BI: bundles | items
        int l = row - R1;
        src = (l < NB) ? (Bf + (size_t)l * D) : (If + (size_t)(l - NB) * D);
    } else {                                // UB: users | bundles
        int l = row - R2;
        src = (l < U) ? (Uf + (size_t)l * D) : (Bf + (size_t)(l - U) * D);
    }
    *(float4*)(f0 + (size_t)row * D + c) = *(const float4*)(src + c);
}

// ---- merged histogram over all 3 edge lists (4 edges/thread) ----
__global__ void hist_kernel(const int* __restrict__ r0, const int* __restrict__ r1,
                            const int* __restrict__ r2,
                            int n0, int n1, int n2, int R1, int R2,
                            int* __restrict__ counts) {
    int base = (blockIdx.x * blockDim.x + threadIdx.x) * 4;
    int ntote = n0 + n1 + n2;
    if (base >= ntote) return;
    if (base + 4 <= n0) {
        int4 r = *(const int4*)(r0 + base);
        atomicAdd(&counts[r.x], 1); atomicAdd(&counts[r.y], 1);
        atomicAdd(&counts[r.z], 1); atomicAdd(&counts[r.w], 1);
    } else if (base >= n0 && base + 4 <= n0 + n1) {
        int4 r = *(const int4*)(r1 + (base - n0));
        atomicAdd(&counts[r.x + R1], 1); atomicAdd(&counts[r.y + R1], 1);
        atomicAdd(&counts[r.z + R1], 1); atomicAdd(&counts[r.w + R1], 1);
    } else if (base >= n0 + n1 && base + 4 <= ntote) {
        int4 r = *(const int4*)(r2 + (base - n0 - n1));
        atomicAdd(&counts[r.x + R2], 1); atomicAdd(&counts[r.y + R2], 1);
        atomicAdd(&counts[r.z + R2], 1); atomicAdd(&counts[r.w + R2], 1);
    } else {
        int end = min(base + 4, ntote);
        for (int k = base; k < end; k++) {
            int row;
            if (k < n0) row = r0[k];
            else if (k < n0 + n1) row = r1[k - n0] + R1;
            else row = r2[k - n0 - n1] + R2;
            atomicAdd(&counts[row], 1);
        }
    }
}

// ---- single-pass decoupled-lookback exclusive scan -> offs + cursor ----
__global__ void scan_kernel(const int* __restrict__ counts, int n,
                            int* __restrict__ offs, int* __restrict__ cursor,
                            unsigned long long* __restrict__ desc,
                            unsigned int* __restrict__ ticket) {
    __shared__ int s_warp[8];
    __shared__ int s_bid;
    __shared__ int s_excl;
    int lane = threadIdx.x & 31;
    int wid = threadIdx.x >> 5;
    if (threadIdx.x == 0) s_bid = (int)atomicAdd(ticket, 1u);
    __syncthreads();
    int bid = s_bid;
    int i = bid * SCAN_B + threadIdx.x;
    int v = (i < n) ? counts[i] : 0;
    int x = v;
    #pragma unroll
    for (int o = 1; o < 32; o <<= 1) {
        int t = __shfl_up_sync(0xffffffffu, x, o);
        if (lane >= o) x += t;
    }
    if (lane == 31) s_warp[wid] = x;
    __syncthreads();
    if (wid == 0 && lane < 8) {
        int w = s_warp[lane];
        #pragma unroll
        for (int o = 1; o < 8; o <<= 1) {
            int t = __shfl_up_sync(0xffu, w, o);
            if (lane >= o) w += t;
        }
        s_warp[lane] = w;
    }
    __syncthreads();
    int incl = x + (wid ? s_warp[wid - 1] : 0);
    int total = s_warp[7];
    if (threadIdx.x == 0) {
        if (bid == 0) {
            atomicExch(&desc[0], (2ULL << 62) | (unsigned long long)(unsigned)total);
            s_excl = 0;
        } else {
            atomicExch(&desc[bid], (1ULL << 62) | (unsigned long long)(unsigned)total);
            int excl = 0;
            int j = bid - 1;
            while (true) {
                unsigned long long d;
                do { d = atomicAdd(&desc[j], 0ULL); } while ((d >> 62) == 0ULL);
                excl += (int)(unsigned)d;
                if ((d >> 62) == 2ULL) break;
                j--;
            }
            s_excl = excl;
            atomicExch(&desc[bid], (2ULL << 62) | (unsigned long long)(unsigned)(excl + total));
        }
    }
    __syncthreads();
    int excl = s_excl;
    if (i < n) {
        int inc = incl + excl;
        offs[i + 1] = inc;
        cursor[i] = inc - v;
        if (i == 0) offs[0] = 0;
    }
}

// ---- merged bucket: edges -> (global col, val), ordered by global row ----
__global__ void bucket_kernel(const int* __restrict__ r0, const int* __restrict__ c0,
                              const float* __restrict__ v0,
                              const int* __restrict__ r1, const int* __restrict__ c1,
                              const float* __restrict__ v1,
                              const int* __restrict__ r2, const int* __restrict__ c2,
                              const float* __restrict__ v2,
                              int n0, int n1, int n2, int R1, int R2,
                              int* __restrict__ cursor, float2* __restrict__ edges) {
    int base = (blockIdx.x * blockDim.x + threadIdx.x) * 4;
    int ntote = n0 + n1 + n2;
    if (base >= ntote) return;
    if (base + 4 <= n0) {
        int4 r = *(const int4*)(r0 + base);
        int4 c = *(const int4*)(c0 + base);
        float4 v = *(const float4*)(v0 + base);
        int p0 = atomicAdd(&cursor[r.x], 1);
        int p1 = atomicAdd(&cursor[r.y], 1);
        int p2 = atomicAdd(&cursor[r.z], 1);
        int p3 = atomicAdd(&cursor[r.w], 1);
        edges[p0] = make_float2(__int_as_float(c.x), v.x);
        edges[p1] = make_float2(__int_as_float(c.y), v.y);
        edges[p2] = make_float2(__int_as_float(c.z), v.z);
        edges[p3] = make_float2(__int_as_float(c.w), v.w);
    } else if (base >= n0 && base + 4 <= n0 + n1) {
        int b = base - n0;
        int4 r = *(const int4*)(r1 + b);
        int4 c = *(const int4*)(c1 + b);
        float4 v = *(const float4*)(v1 + b);
        int p0 = atomicAdd(&cursor[r.x + R1], 1);
        int p1 = atomicAdd(&cursor[r.y + R1], 1);
        int p2 = atomicAdd(&cursor[r.z + R1], 1);
        int p3 = atomicAdd(&cursor[r.w + R1], 1);
        edges[p0] = make_float2(__int_as_float(c.x + R1), v.x);
        edges[p1] = make_float2(__int_as_float(c.y + R1), v.y);
        edges[p2] = make_float2(__int_as_float(c.z + R1), v.z);
        edges[p3] = make_float2(__int_as_float(c.w + R1), v.w);
    } else if (base >= n0 + n1 && base + 4 <= ntote) {
        int b = base - n0 - n1;
        int4 r = *(const int4*)(r2 + b);
        int4 c = *(const int4*)(c2 + b);
        float4 v = *(const float4*)(v2 + b);
        int p0 = atomicAdd(&cursor[r.x + R2], 1);
        int p1 = atomicAdd(&cursor[r.y + R2], 1);
        int p2 = atomicAdd(&cursor[r.z + R2], 1);
        int p3 = atomicAdd(&cursor[r.w + R2], 1);
        edges[p0] = make_float2(__int_as_float(c.x + R2), v.x);
        edges[p1] = make_float2(__int_as_float(c.y + R2), v.y);
        edges[p2] = make_float2(__int_as_float(c.z + R2), v.z);
        edges[p3] = make_float2(__int_as_float(c.w + R2), v.w);
    } else {
        int end = min(base + 4, ntote);
        for (int k = base; k < end; k++) {
            int row, col; float val;
            if (k < n0) { row = r0[k]; col = c0[k]; val = v0[k]; }
            else if (k < n0 + n1) { int b = k - n0; row = r1[b] + R1; col = c1[b] + R1; val = v1[b]; }
            else { int b = k - n0 - n1; row = r2[b] + R2; col = c2[b] + R2; val = v2[b]; }
            int pos = atomicAdd(&cursor[row], 1);
            edges[pos] = make_float2(__int_as_float(col), val);
        }
    }
}

// ---- fused gather-SpMM + L2 normalize + output accumulate ----
// Warp per row. Two 16-lane halves; lane owns float4 chunk (lane&15), halves
// process alternating edges; combined via shfl_xor(16).
// FIRST: gathers f0, writes fnext(=f1), out = f0row/3 + norm/3 (pure store)
// else : gathers f1, out += norm/3 (RMW)
template <bool FIRST>
__global__ void spmm_kernel(const float2* __restrict__ edges, const int* __restrict__ offs,
                            const float* __restrict__ fin, float* __restrict__ fnext,
                            int rbase, int n, int nA,
                            float* __restrict__ outA, float* __restrict__ outB) {
    int wrow = (int)((blockIdx.x * blockDim.x + threadIdx.x) >> 5);
    if (wrow >= n) return;
    int row = rbase + wrow;
    int lane = threadIdx.x & 31;
    int chunk = lane & 15;
    int half = lane >> 4;
    int s = offs[row], e = offs[row + 1];

    float4 a0 = make_float4(0.f, 0.f, 0.f, 0.f);
    float4 a1 = a0;
    int i = s + half;
    for (; i + 2 < e; i += 4) {
        float2 h0 = edges[i];
        float2 h1 = edges[i + 2];
        float4 x0 = *((const float4*)(fin + (size_t)__float_as_int(h0.x) * D) + chunk);
        float4 x1 = *((const float4*)(fin + (size_t)__float_as_int(h1.x) * D) + chunk);
        a0.x += h0.y * x0.x; a0.y += h0.y * x0.y; a0.z += h0.y * x0.z; a0.w += h0.y * x0.w;
        a1.x += h1.y * x1.x; a1.y += h1.y * x1.y; a1.z += h1.y * x1.z; a1.w += h1.y * x1.w;
    }
    if (i < e) {
        float2 h = edges[i];
        float4 x = *((const float4*)(fin + (size_t)__float_as_int(h.x) * D) + chunk);
        a0.x += h.y * x.x; a0.y += h.y * x.y; a0.z += h.y * x.z; a0.w += h.y * x.w;
    }
    float4 a = make_float4(a0.x + a1.x, a0.y + a1.y, a0.z + a1.z, a0.w + a1.w);
    // combine the two halves: both end up with the full chunk value
    a.x += __shfl_xor_sync(0xffffffffu, a.x, 16);
    a.y += __shfl_xor_sync(0xffffffffu, a.y, 16);
    a.z += __shfl_xor_sync(0xffffffffu, a.z, 16);
    a.w += __shfl_xor_sync(0xffffffffu, a.w, 16);
    // norm reduce over the 16 chunks (within each half)
    float ss = a.x * a.x + a.y * a.y + a.z * a.z + a.w * a.w;
    #pragma unroll
    for (int o = 8; o; o >>= 1) ss += __shfl_xor_sync(0xffffffffu, ss, o);
    const float k = 1.0f / 3.0f;
    float scale = k / fmaxf(sqrtf(ss), 1e-12f);

    float* dst = (wrow < nA) ? (outA + (size_t)wrow * D)
                             : (outB + (size_t)(wrow - nA) * D);
    if (FIRST) {
        if (half == 0) {
            *((float4*)(fnext + (size_t)row * D) + chunk) = a;
        } else {
            float4 f = *((const float4*)(fin + (size_t)row * D) + chunk);
            float4 o = make_float4(f.x * k + a.x * scale, f.y * k + a.y * scale,
                                   f.z * k + a.z * scale, f.w * k + a.w * scale);
            *((float4*)dst + chunk) = o;
        }
    } else {
        if (half == 0) {
            float4* d = (float4*)dst + chunk;
            float4 o = *d;
            o.x += a.x * scale; o.y += a.y * scale;
            o.z += a.z * scale; o.w += a.w * scale;
            *d = o;
        }
    }
}

extern "C" void kernel_launch(void* const* d_in, const int* in_sizes, int n_in,
                              void* d_out, int out_size) {
    const float* users_feature   = (const float*)d_in[0];
    const float* items_feature   = (const float*)d_in[1];
    const float* bundles_feature = (const float*)d_in[2];
    const float* ui_vals = (const float*)d_in[3];
    const float* bi_vals = (const float*)d_in[4];
    const float* ub_vals = (const float*)d_in[5];
    const int* ui_rows = (const int*)d_in[6];
    const int* ui_cols = (const int*)d_in[7];
    const int* bi_rows = (const int*)d_in[8];
    const int* bi_cols = (const int*)d_in[9];
    const int* ub_rows = (const int*)d_in[10];
    const int* ub_cols = (const int*)d_in[11];

    int U  = in_sizes[0] / D;
    int NI = in_sizes[1] / D;
    int NB = in_sizes[2] / D;
    int n0 = in_sizes[3];   // nnz UI
    int n1 = in_sizes[4];   // nnz BI
    int n2 = in_sizes[5];   // nnz UB

    int R1 = U + NI;             // BI row base
    int R2 = R1 + NB + NI;       // UB row base
    int ntot = R2 + U + NB;      // 340000
    int ntote = n0 + n1 + n2;    // 4M

    float* out = (float*)d_out;

    float *f0, *f1;
    float2* edges;
    int *counts, *offs, *cursor;
    unsigned long long* desc;
    unsigned int* ticket;
    cudaGetSymbolAddress((void**)&f0, g_f0);
    cudaGetSymbolAddress((void**)&f1, g_f1);
    cudaGetSymbolAddress((void**)&edges, g_edges);
    cudaGetSymbolAddress((void**)&counts, g_counts);
    cudaGetSymbolAddress((void**)&offs, g_offs);
    cudaGetSymbolAddress((void**)&cursor, g_cursor);
    cudaGetSymbolAddress((void**)&desc, g_desc);
    cudaGetSymbolAddress((void**)&ticket, g_ticket);

    // Output layout: [UI_u(U), UB_u(U), BI_b(NB), UB_b(NB), UI_i(NI), BI_i(NI)]
    float* o_ui_u = out;
    float* o_ub_u = out + (size_t)U * D;
    float* o_bi_b = out + (size_t)2 * U * D;
    float* o_ub_b = out + ((size_t)2 * U + NB) * D;
    float* o_ui_i = out + ((size_t)2 * U + 2 * NB) * D;
    float* o_bi_i = out + ((size_t)2 * U + 2 * NB + NI) * D;

    int nb = (ntot + SCAN_B - 1) / SCAN_B;
    cudaMemsetAsync(counts, 0, (size_t)ntot * sizeof(int), 0);
    cudaMemsetAsync(desc, 0, (size_t)nb * sizeof(unsigned long long), 0);
    cudaMemsetAsync(ticket, 0, sizeof(unsigned int), 0);

    init_kernel<<<(ntot * (D / 4) + 255) / 256, 256>>>(
        users_feature, items_feature, bundles_feature, U, NB, R1, R2, ntot, f0);

    int eth = (ntote + 3) / 4;
    hist_kernel<<<(eth + 255) / 256, 256>>>(ui_rows, bi_rows, ub_rows,
                                            n0, n1, n2, R1, R2, counts);
    scan_kernel<<<nb, SCAN_B>>>(counts, ntot, offs, cursor, desc, ticket);
    bucket_kernel<<<(eth + 255) / 256, 256>>>(
        ui_rows, ui_cols, ui_vals, bi_rows, bi_cols, bi_vals,
        ub_rows, ub_cols, ub_vals, n0, n1, n2, R1, R2, cursor, edges);

    // Per-graph SpMM (keeps each working set L2-resident); layers back-to-back.
    struct G { int rbase, n, nA; float *oA, *oB; };
    G gs[3] = {
        {0,  U + NI,  U,  o_ui_u, o_ui_i},
        {R1, NB + NI, NB, o_bi_b, o_bi_i},
        {R2, U + NB,  U,  o_ub_u, o_ub_b},
    };
    for (int g = 0; g < 3; g++) {
        int blocks = (gs[g].n + 7) / 8;
        spmm_kernel<true><<<blocks, 256>>>(edges, offs, f0, f1,
                                           gs[g].rbase, gs[g].n, gs[g].nA,
                                           gs[g].oA, gs[g].oB);
        spmm_kernel<false><<<blocks, 256>>>(edges, offs, f1, nullptr,
                                            gs[g].rbase, gs[g].n, gs[g].nA,
                                            gs[g].oA, gs[g].oB);
    }
}

// round 5
// speedup vs baseline: 1.1653x; 1.1409x over previous
#include <cuda_runtime.h>
#include <cstdint>

#define D 64
#define MAXNTOT 340008
#define MAXNNZALL 4000008
#define SCAN_B 256
#define MAXBLKS ((150016 + SCAN_B - 1) / SCAN_B)   // per-graph max rows 150000

// ---- scratch (__device__ globals; no allocation allowed) ----
__device__ __align__(16) float g_f0[(size_t)MAXNTOT * D];   // ~87 MB
__device__ __align__(16) float g_f1[(size_t)MAXNTOT * D];   // ~87 MB
__device__ __align__(16) float2 g_edges[MAXNNZALL];         // {local col bits, val}
__device__ int g_counts[MAXNTOT];
__device__ int g_offs[MAXNTOT + 8];
__device__ int g_cursor[MAXNTOT];
__device__ unsigned long long g_desc[3][MAXBLKS];
__device__ unsigned int g_ticket[3];

// ---- init: f0 = concat of all three propagation inputs (global row space) ----
__global__ void init_kernel(const float* __restrict__ Uf, const float* __restrict__ If,
                            const float* __restrict__ Bf,
                            int U, int NB, int R1, int R2, int ntot,
                            float* __restrict__ f0) {
    int idx = blockIdx.x * blockDim.x + threadIdx.x;   // one float4 per thread
    if (idx >= ntot * (D / 4)) return;
    int row = idx >> 4;
    int c = (idx & 15) * 4;
    const float* src;
    if (row < R1) {                         // UI: users | items
        src = (row < U) ? (Uf + (size_t)row * D) : (If + (size_t)(row - U) * D);
    } else if (row < R2) {                  // BI: bundles | items
        int l = row - R1;
        src = (l < NB) ? (Bf + (size_t)l * D) : (If + (size_t)(l - NB) * D);
    } else {                                // UB: users | bundles
        int l = row - R2;
        src = (l < U) ? (Uf + (size_t)l * D) : (Bf + (size_t)(l - U) * D);
    }
    *(float4*)(f0 + (size_t)row * D + c) = *(const float4*)(src + c);
}

// ---- per-graph histogram (4 edges/thread) ----
__global__ void hist_kernel(const int* __restrict__ rows, int nnz, int* __restrict__ counts) {
    int base = (blockIdx.x * blockDim.x + threadIdx.x) * 4;
    if (base + 4 <= nnz) {
        int4 r = *(const int4*)(rows + base);
        atomicAdd(&counts[r.x], 1); atomicAdd(&counts[r.y], 1);
        atomicAdd(&counts[r.z], 1); atomicAdd(&counts[r.w], 1);
    } else {
        for (int k = base; k < nnz; k++) atomicAdd(&counts[rows[k]], 1);
    }
}

// ---- single-pass decoupled-lookback exclusive scan -> offs + cursor ----
__global__ void scan_kernel(const int* __restrict__ counts, int n,
                            int* __restrict__ offs, int* __restrict__ cursor,
                            unsigned long long* __restrict__ desc,
                            unsigned int* __restrict__ ticket) {
    __shared__ int s_warp[8];
    __shared__ int s_bid;
    __shared__ int s_excl;
    int lane = threadIdx.x & 31;
    int wid = threadIdx.x >> 5;
    if (threadIdx.x == 0) s_bid = (int)atomicAdd(ticket, 1u);
    __syncthreads();
    int bid = s_bid;
    int i = bid * SCAN_B + threadIdx.x;
    int v = (i < n) ? counts[i] : 0;
    int x = v;
    #pragma unroll
    for (int o = 1; o < 32; o <<= 1) {
        int t = __shfl_up_sync(0xffffffffu, x, o);
        if (lane >= o) x += t;
    }
    if (lane == 31) s_warp[wid] = x;
    __syncthreads();
    if (wid == 0 && lane < 8) {
        int w = s_warp[lane];
        #pragma unroll
        for (int o = 1; o < 8; o <<= 1) {
            int t = __shfl_up_sync(0xffu, w, o);
            if (lane >= o) w += t;
        }
        s_warp[lane] = w;
    }
    __syncthreads();
    int incl = x + (wid ? s_warp[wid - 1] : 0);
    int total = s_warp[7];
    if (threadIdx.x == 0) {
        if (bid == 0) {
            atomicExch(&desc[0], (2ULL << 62) | (unsigned long long)(unsigned)total);
            s_excl = 0;
        } else {
            atomicExch(&desc[bid], (1ULL << 62) | (unsigned long long)(unsigned)total);
            int excl = 0;
            int j = bid - 1;
            while (true) {
                unsigned long long d;
                do { d = atomicAdd(&desc[j], 0ULL); } while ((d >> 62) == 0ULL);
                excl += (int)(unsigned)d;
                if ((d >> 62) == 2ULL) break;
                j--;
            }
            s_excl = excl;
            atomicExch(&desc[bid], (2ULL << 62) | (unsigned long long)(unsigned)(excl + total));
        }
    }
    __syncthreads();
    int excl = s_excl;
    if (i < n) {
        int inc = incl + excl;
        offs[i + 1] = inc;
        cursor[i] = inc - v;
        if (i == 0) offs[0] = 0;
    }
}

// ---- per-graph bucket: edges -> (local col, val), ordered by row ----
__global__ void bucket_kernel(const int* __restrict__ rows, const int* __restrict__ cols,
                              const float* __restrict__ vals, int nnz,
                              int* __restrict__ cursor, float2* __restrict__ edges) {
    int base = (blockIdx.x * blockDim.x + threadIdx.x) * 4;
    if (base + 4 <= nnz) {
        int4 r = *(const int4*)(rows + base);
        int4 c = *(const int4*)(cols + base);
        float4 v = *(const float4*)(vals + base);
        int p0 = atomicAdd(&cursor[r.x], 1);
        int p1 = atomicAdd(&cursor[r.y], 1);
        int p2 = atomicAdd(&cursor[r.z], 1);
        int p3 = atomicAdd(&cursor[r.w], 1);
        edges[p0] = make_float2(__int_as_float(c.x), v.x);
        edges[p1] = make_float2(__int_as_float(c.y), v.y);
        edges[p2] = make_float2(__int_as_float(c.z), v.z);
        edges[p3] = make_float2(__int_as_float(c.w), v.w);
    } else {
        for (int k = base; k < nnz; k++) {
            int pos = atomicAdd(&cursor[rows[k]], 1);
            edges[pos] = make_float2(__int_as_float(cols[k]), vals[k]);
        }
    }
}

// ---- fused gather-SpMM + L2 normalize + output accumulate ----
// Warp per row. Two 16-lane halves; lane owns float4 chunk (lane&15).
// Each half processes a CONTIGUOUS half of the row's edges with 4-way unroll
// (8 independent gathers in flight per warp); halves merged via shfl_xor(16).
template <bool FIRST>
__global__ void spmm_kernel(const float2* __restrict__ edges, const int* __restrict__ offs,
                            const float* __restrict__ fin, float* __restrict__ fnext,
                            int rbase, int n, int nA,
                            float* __restrict__ outA, float* __restrict__ outB) {
    int wrow = (int)((blockIdx.x * blockDim.x + threadIdx.x) >> 5);
    if (wrow >= n) return;
    int lane = threadIdx.x & 31;
    int chunk = lane & 15;
    int half = lane >> 4;
    int s = offs[wrow], e = offs[wrow + 1];
    int mid = s + (((e - s) + 1) >> 1);
    int lo = half ? mid : s;
    int hi = half ? e : mid;
    const float* fb = fin + (size_t)rbase * D;   // local col -> global row

    float4 acc0 = make_float4(0.f, 0.f, 0.f, 0.f);
    float4 acc1 = acc0;
    int i = lo;
    for (; i + 4 <= hi; i += 4) {
        float2 e0 = __ldg(edges + i);
        float2 e1 = __ldg(edges + i + 1);
        float2 e2 = __ldg(edges + i + 2);
        float2 e3 = __ldg(edges + i + 3);
        float4 x0 = *((const float4*)(fb + (size_t)__float_as_int(e0.x) * D) + chunk);
        float4 x1 = *((const float4*)(fb + (size_t)__float_as_int(e1.x) * D) + chunk);
        float4 x2 = *((const float4*)(fb + (size_t)__float_as_int(e2.x) * D) + chunk);
        float4 x3 = *((const float4*)(fb + (size_t)__float_as_int(e3.x) * D) + chunk);
        acc0.x += e0.y * x0.x; acc0.y += e0.y * x0.y; acc0.z += e0.y * x0.z; acc0.w += e0.y * x0.w;
        acc1.x += e1.y * x1.x; acc1.y += e1.y * x1.y; acc1.z += e1.y * x1.z; acc1.w += e1.y * x1.w;
        acc0.x += e2.y * x2.x; acc0.y += e2.y * x2.y; acc0.z += e2.y * x2.z; acc0.w += e2.y * x2.w;
        acc1.x += e3.y * x3.x; acc1.y += e3.y * x3.y; acc1.z += e3.y * x3.z; acc1.w += e3.y * x3.w;
    }
    for (; i < hi; i++) {
        float2 h = __ldg(edges + i);
        float4 x = *((const float4*)(fb + (size_t)__float_as_int(h.x) * D) + chunk);
        acc0.x += h.y * x.x; acc0.y += h.y * x.y; acc0.z += h.y * x.z; acc0.w += h.y * x.w;
    }
    float4 a = make_float4(acc0.x + acc1.x, acc0.y + acc1.y,
                           acc0.z + acc1.z, acc0.w + acc1.w);
    a.x += __shfl_xor_sync(0xffffffffu, a.x, 16);
    a.y += __shfl_xor_sync(0xffffffffu, a.y, 16);
    a.z += __shfl_xor_sync(0xffffffffu, a.z, 16);
    a.w += __shfl_xor_sync(0xffffffffu, a.w, 16);
    float ss = a.x * a.x + a.y * a.y + a.z * a.z + a.w * a.w;
    #pragma unroll
    for (int o = 8; o; o >>= 1) ss += __shfl_xor_sync(0xffffffffu, ss, o);
    const float k = 1.0f / 3.0f;
    float scale = k / fmaxf(sqrtf(ss), 1e-12f);

    float* dst = (wrow < nA) ? (outA + (size_t)wrow * D)
                             : (outB + (size_t)(wrow - nA) * D);
    if (FIRST) {
        if (half == 0) {
            *((float4*)(fnext + (size_t)(rbase + wrow) * D) + chunk) = a;
        } else {
            float4 f = *((const float4*)(fb + (size_t)wrow * D) + chunk);
            *((float4*)dst + chunk) = make_float4(
                f.x * k + a.x * scale, f.y * k + a.y * scale,
                f.z * k + a.z * scale, f.w * k + a.w * scale);
        }
    } else {
        if (half == 0) {
            float4* d = (float4*)dst + chunk;
            float4 o = *d;
            o.x += a.x * scale; o.y += a.y * scale;
            o.z += a.z * scale; o.w += a.w * scale;
            *d = o;
        }
    }
}

// ---- persistent streams/events (created once; identical work every call) ----
static cudaStream_t s_strm[3];
static cudaEvent_t s_root, s_init, s_done[3];
static bool s_ready = false;

extern "C" void kernel_launch(void* const* d_in, const int* in_sizes, int n_in,
                              void* d_out, int out_size) {
    const float* users_feature   = (const float*)d_in[0];
    const float* items_feature   = (const float*)d_in[1];
    const float* bundles_feature = (const float*)d_in[2];
    const float* vals_[3] = {(const float*)d_in[3], (const float*)d_in[4], (const float*)d_in[5]};
    const int* rows_[3] = {(const int*)d_in[6], (const int*)d_in[8], (const int*)d_in[10]};
    const int* cols_[3] = {(const int*)d_in[7], (const int*)d_in[9], (const int*)d_in[11]};

    int U  = in_sizes[0] / D;
    int NI = in_sizes[1] / D;
    int NB = in_sizes[2] / D;
    int nnz_[3] = {in_sizes[3], in_sizes[4], in_sizes[5]};   // UI, BI, UB

    int R1 = U + NI;             // BI row base
    int R2 = R1 + NB + NI;       // UB row base
    int ntot = R2 + U + NB;

    if (!s_ready) {
        for (int g = 0; g < 3; g++) {
            cudaStreamCreateWithFlags(&s_strm[g], cudaStreamNonBlocking);
            cudaEventCreateWithFlags(&s_done[g], cudaEventDisableTiming);
        }
        cudaEventCreateWithFlags(&s_root, cudaEventDisableTiming);
        cudaEventCreateWithFlags(&s_init, cudaEventDisableTiming);
        s_ready = true;
    }

    float* out = (float*)d_out;
    float *f0, *f1;
    float2* edges;
    int *counts, *offs, *cursor;
    unsigned long long* desc;
    unsigned int* ticket;
    cudaGetSymbolAddress((void**)&f0, g_f0);
    cudaGetSymbolAddress((void**)&f1, g_f1);
    cudaGetSymbolAddress((void**)&edges, g_edges);
    cudaGetSymbolAddress((void**)&counts, g_counts);
    cudaGetSymbolAddress((void**)&offs, g_offs);
    cudaGetSymbolAddress((void**)&cursor, g_cursor);
    cudaGetSymbolAddress((void**)&desc, g_desc);
    cudaGetSymbolAddress((void**)&ticket, g_ticket);

    // Output layout: [UI_u(U), UB_u(U), BI_b(NB), UB_b(NB), UI_i(NI), BI_i(NI)]
    float* o_ui_u = out;
    float* o_ub_u = out + (size_t)U * D;
    float* o_bi_b = out + (size_t)2 * U * D;
    float* o_ub_b = out + ((size_t)2 * U + NB) * D;
    float* o_ui_i = out + ((size_t)2 * U + 2 * NB) * D;
    float* o_bi_i = out + ((size_t)2 * U + 2 * NB + NI) * D;

    struct G { int rbase, n, nA, ebase; float *oA, *oB; };
    G gs[3] = {
        {0,  U + NI,  U,  0,                   o_ui_u, o_ui_i},
        {R1, NB + NI, NB, nnz_[0],             o_bi_b, o_bi_i},
        {R2, U + NB,  U,  nnz_[0] + nnz_[1],   o_ub_u, o_ub_b},
    };

    // root fork point, then init (whole f0) on the main stream
    cudaEventRecord(s_root, 0);
    init_kernel<<<(ntot * (D / 4) + 255) / 256, 256>>>(
        users_feature, items_feature, bundles_feature, U, NB, R1, R2, ntot, f0);
    cudaEventRecord(s_init, 0);

    for (int g = 0; g < 3; g++) {
        cudaStream_t st = s_strm[g];
        const G& G_ = gs[g];
        int n = G_.n;
        int nb = (n + SCAN_B - 1) / SCAN_B;
        int* cnt = counts + G_.rbase;
        int* off = offs + G_.rbase + g;        // +g pad avoids boundary overlap
        int* cur = cursor + G_.rbase;
        float2* edg = edges + G_.ebase;
        unsigned long long* dsc = desc + (size_t)g * MAXBLKS;
        unsigned int* tkt = ticket + g;

        cudaStreamWaitEvent(st, s_root, 0);
        cudaMemsetAsync(cnt, 0, (size_t)n * sizeof(int), st);
        cudaMemsetAsync(dsc, 0, (size_t)nb * sizeof(unsigned long long), st);
        cudaMemsetAsync(tkt, 0, sizeof(unsigned int), st);

        int eth = (nnz_[g] + 3) / 4;
        hist_kernel<<<(eth + 255) / 256, 256, 0, st>>>(rows_[g], nnz_[g], cnt);
        scan_kernel<<<nb, SCAN_B, 0, st>>>(cnt, n, off, cur, dsc, tkt);
        bucket_kernel<<<(eth + 255) / 256, 256, 0, st>>>(rows_[g], cols_[g], vals_[g],
                                                         nnz_[g], cur, edg);

        cudaStreamWaitEvent(st, s_init, 0);   // spmm needs f0
        int blocks = (n + 7) / 8;
        spmm_kernel<true><<<blocks, 256, 0, st>>>(edg, off, f0, f1,
                                                  G_.rbase, n, G_.nA, G_.oA, G_.oB);
        spmm_kernel<false><<<blocks, 256, 0, st>>>(edg, off, f1, nullptr,
                                                   G_.rbase, n, G_.nA, G_.oA, G_.oB);
        cudaEventRecord(s_done[g], st);
    }

    for (int g = 0; g < 3; g++)
        cudaStreamWaitEvent(0, s_done[g], 0);   // join back to main stream
}

// round 6
// speedup vs baseline: 1.2033x; 1.0327x over previous
#include <cuda_runtime.h>
#include <cuda_fp16.h>
#include <cstdint>

#define D 64
#define MAXNTOT 340008
#define MAXNNZALL 4000008
#define SCAN_B 256
#define MAXBLKS ((150016 + SCAN_B - 1) / SCAN_B)   // per-graph max rows

// ---- scratch (__device__ globals; no allocation allowed) ----
__device__ __align__(16) __half g_f0[(size_t)MAXNTOT * D];   // ~43.5 MB
__device__ __align__(16) __half g_f1[(size_t)MAXNTOT * D];   // ~43.5 MB
__device__ __align__(16) float2 g_edges[MAXNNZALL];          // {local col bits, val}
__device__ int g_counts[MAXNTOT];
__device__ int g_offs[MAXNTOT + 8];
__device__ int g_cursor[MAXNTOT];
__device__ unsigned long long g_desc[3][MAXBLKS];
__device__ unsigned int g_ticket[3];

// ---- init: f0(fp16) = concat of all three propagation inputs ----
__global__ void init_kernel(const float* __restrict__ Uf, const float* __restrict__ If,
                            const float* __restrict__ Bf,
                            int U, int NB, int R1, int R2, int ntot,
                            __half* __restrict__ f0) {
    int idx = blockIdx.x * blockDim.x + threadIdx.x;   // one float4 -> 4 halves
    if (idx >= ntot * (D / 4)) return;
    int row = idx >> 4;
    int c = (idx & 15) * 4;
    const float* src;
    if (row < R1) {
        src = (row < U) ? (Uf + (size_t)row * D) : (If + (size_t)(row - U) * D);
    } else if (row < R2) {
        int l = row - R1;
        src = (l < NB) ? (Bf + (size_t)l * D) : (If + (size_t)(l - NB) * D);
    } else {
        int l = row - R2;
        src = (l < U) ? (Uf + (size_t)l * D) : (Bf + (size_t)(l - U) * D);
    }
    float4 v = *(const float4*)(src + c);
    __half2 h0 = __floats2half2_rn(v.x, v.y);
    __half2 h1 = __floats2half2_rn(v.z, v.w);
    uint2 packed;
    packed.x = *(const unsigned int*)&h0;
    packed.y = *(const unsigned int*)&h1;
    *(uint2*)(f0 + (size_t)row * D + c) = packed;
}

// ---- per-graph histogram (8 edges/thread for MLP) ----
__global__ void hist_kernel(const int* __restrict__ rows, int nnz, int* __restrict__ counts) {
    int base = (blockIdx.x * blockDim.x + threadIdx.x) * 8;
    if (base + 8 <= nnz) {
        int4 r0 = *(const int4*)(rows + base);
        int4 r1 = *(const int4*)(rows + base + 4);
        atomicAdd(&counts[r0.x], 1); atomicAdd(&counts[r0.y], 1);
        atomicAdd(&counts[r0.z], 1); atomicAdd(&counts[r0.w], 1);
        atomicAdd(&counts[r1.x], 1); atomicAdd(&counts[r1.y], 1);
        atomicAdd(&counts[r1.z], 1); atomicAdd(&counts[r1.w], 1);
    } else {
        for (int k = base; k < nnz; k++) atomicAdd(&counts[rows[k]], 1);
    }
}

// ---- single-pass decoupled-lookback exclusive scan -> offs + cursor ----
__global__ void scan_kernel(const int* __restrict__ counts, int n,
                            int* __restrict__ offs, int* __restrict__ cursor,
                            unsigned long long* __restrict__ desc,
                            unsigned int* __restrict__ ticket) {
    __shared__ int s_warp[8];
    __shared__ int s_bid;
    __shared__ int s_excl;
    int lane = threadIdx.x & 31;
    int wid = threadIdx.x >> 5;
    if (threadIdx.x == 0) s_bid = (int)atomicAdd(ticket, 1u);
    __syncthreads();
    int bid = s_bid;
    int i = bid * SCAN_B + threadIdx.x;
    int v = (i < n) ? counts[i] : 0;
    int x = v;
    #pragma unroll
    for (int o = 1; o < 32; o <<= 1) {
        int t = __shfl_up_sync(0xffffffffu, x, o);
        if (lane >= o) x += t;
    }
    if (lane == 31) s_warp[wid] = x;
    __syncthreads();
    if (wid == 0 && lane < 8) {
        int w = s_warp[lane];
        #pragma unroll
        for (int o = 1; o < 8; o <<= 1) {
            int t = __shfl_up_sync(0xffu, w, o);
            if (lane >= o) w += t;
        }
        s_warp[lane] = w;
    }
    __syncthreads();
    int incl = x + (wid ? s_warp[wid - 1] : 0);
    int total = s_warp[7];
    if (threadIdx.x == 0) {
        if (bid == 0) {
            atomicExch(&desc[0], (2ULL << 62) | (unsigned long long)(unsigned)total);
            s_excl = 0;
        } else {
            atomicExch(&desc[bid], (1ULL << 62) | (unsigned long long)(unsigned)total);
            int excl = 0;
            int j = bid - 1;
            while (true) {
                unsigned long long d;
                do { d = atomicAdd(&desc[j], 0ULL); } while ((d >> 62) == 0ULL);
                excl += (int)(unsigned)d;
                if ((d >> 62) == 2ULL) break;
                j--;
            }
            s_excl = excl;
            atomicExch(&desc[bid], (2ULL << 62) | (unsigned long long)(unsigned)(excl + total));
        }
    }
    __syncthreads();
    int excl = s_excl;
    if (i < n) {
        int inc = incl + excl;
        offs[i + 1] = inc;
        cursor[i] = inc - v;
        if (i == 0) offs[0] = 0;
    }
}

// ---- per-graph bucket (8 edges/thread for MLP) ----
__global__ void bucket_kernel(const int* __restrict__ rows, const int* __restrict__ cols,
                              const float* __restrict__ vals, int nnz,
                              int* __restrict__ cursor, float2* __restrict__ edges) {
    int base = (blockIdx.x * blockDim.x + threadIdx.x) * 8;
    if (base + 8 <= nnz) {
        int4 ra = *(const int4*)(rows + base);
        int4 rb = *(const int4*)(rows + base + 4);
        int4 ca = *(const int4*)(cols + base);
        int4 cb = *(const int4*)(cols + base + 4);
        float4 va = *(const float4*)(vals + base);
        float4 vb = *(const float4*)(vals + base + 4);
        int p0 = atomicAdd(&cursor[ra.x], 1);
        int p1 = atomicAdd(&cursor[ra.y], 1);
        int p2 = atomicAdd(&cursor[ra.z], 1);
        int p3 = atomicAdd(&cursor[ra.w], 1);
        int p4 = atomicAdd(&cursor[rb.x], 1);
        int p5 = atomicAdd(&cursor[rb.y], 1);
        int p6 = atomicAdd(&cursor[rb.z], 1);
        int p7 = atomicAdd(&cursor[rb.w], 1);
        edges[p0] = make_float2(__int_as_float(ca.x), va.x);
        edges[p1] = make_float2(__int_as_float(ca.y), va.y);
        edges[p2] = make_float2(__int_as_float(ca.z), va.z);
        edges[p3] = make_float2(__int_as_float(ca.w), va.w);
        edges[p4] = make_float2(__int_as_float(cb.x), vb.x);
        edges[p5] = make_float2(__int_as_float(cb.y), vb.y);
        edges[p6] = make_float2(__int_as_float(cb.z), vb.z);
        edges[p7] = make_float2(__int_as_float(cb.w), vb.w);
    } else {
        for (int k = base; k < nnz; k++) {
            int pos = atomicAdd(&cursor[rows[k]], 1);
            edges[pos] = make_float2(__int_as_float(cols[k]), vals[k]);
        }
    }
}

// ---- fused gather-SpMM (fp16 features, fp32 accum) + L2 norm + output ----
// Warp per row; lane owns 4 halves (chunk = lane&15, uint2 gather);
// two 16-lane halves each take a contiguous half of the edges, 4-way unrolled.
template <bool FIRST>
__global__ void spmm_kernel(const float2* __restrict__ edges, const int* __restrict__ offs,
                            const __half* __restrict__ fin, __half* __restrict__ fnext,
                            int rbase, int n, int nA,
                            float* __restrict__ outA, float* __restrict__ outB) {
    int wrow = (int)((blockIdx.x * blockDim.x + threadIdx.x) >> 5);
    if (wrow >= n) return;
    int lane = threadIdx.x & 31;
    int chunk = lane & 15;
    int half = lane >> 4;
    int s = offs[wrow], e = offs[wrow + 1];
    int mid = s + (((e - s) + 1) >> 1);
    int lo = half ? mid : s;
    int hi = half ? e : mid;
    const __half* fb = fin + (size_t)rbase * D;

    float4 acc0 = make_float4(0.f, 0.f, 0.f, 0.f);
    float4 acc1 = acc0;
    int i = lo;
    for (; i + 4 <= hi; i += 4) {
        float2 e0 = __ldg(edges + i);
        float2 e1 = __ldg(edges + i + 1);
        float2 e2 = __ldg(edges + i + 2);
        float2 e3 = __ldg(edges + i + 3);
        uint2 r0 = *((const uint2*)(fb + (size_t)__float_as_int(e0.x) * D) + chunk);
        uint2 r1 = *((const uint2*)(fb + (size_t)__float_as_int(e1.x) * D) + chunk);
        uint2 r2 = *((const uint2*)(fb + (size_t)__float_as_int(e2.x) * D) + chunk);
        uint2 r3 = *((const uint2*)(fb + (size_t)__float_as_int(e3.x) * D) + chunk);
        float2 a0 = __half22float2(*(__half2*)&r0.x), b0 = __half22float2(*(__half2*)&r0.y);
        float2 a1 = __half22float2(*(__half2*)&r1.x), b1 = __half22float2(*(__half2*)&r1.y);
        float2 a2 = __half22float2(*(__half2*)&r2.x), b2 = __half22float2(*(__half2*)&r2.y);
        float2 a3 = __half22float2(*(__half2*)&r3.x), b3 = __half22float2(*(__half2*)&r3.y);
        acc0.x += e0.y * a0.x; acc0.y += e0.y * a0.y; acc0.z += e0.y * b0.x; acc0.w += e0.y * b0.y;
        acc1.x += e1.y * a1.x; acc1.y += e1.y * a1.y; acc1.z += e1.y * b1.x; acc1.w += e1.y * b1.y;
        acc0.x += e2.y * a2.x; acc0.y += e2.y * a2.y; acc0.z += e2.y * b2.x; acc0.w += e2.y * b2.y;
        acc1.x += e3.y * a3.x; acc1.y += e3.y * a3.y; acc1.z += e3.y * b3.x; acc1.w += e3.y * b3.y;
    }
    for (; i < hi; i++) {
        float2 h = __ldg(edges + i);
        uint2 r = *((const uint2*)(fb + (size_t)__float_as_int(h.x) * D) + chunk);
        float2 a = __half22float2(*(__half2*)&r.x), b = __half22float2(*(__half2*)&r.y);
        acc0.x += h.y * a.x; acc0.y += h.y * a.y; acc0.z += h.y * b.x; acc0.w += h.y * b.y;
    }
    float4 a = make_float4(acc0.x + acc1.x, acc0.y + acc1.y,
                           acc0.z + acc1.z, acc0.w + acc1.w);
    a.x += __shfl_xor_sync(0xffffffffu, a.x, 16);
    a.y += __shfl_xor_sync(0xffffffffu, a.y, 16);
    a.z += __shfl_xor_sync(0xffffffffu, a.z, 16);
    a.w += __shfl_xor_sync(0xffffffffu, a.w, 16);
    float ss = a.x * a.x + a.y * a.y + a.z * a.z + a.w * a.w;
    #pragma unroll
    for (int o = 8; o; o >>= 1) ss += __shfl_xor_sync(0xffffffffu, ss, o);
    const float k = 1.0f / 3.0f;
    float scale = k / fmaxf(sqrtf(ss), 1e-12f);

    float* dst = (wrow < nA) ? (outA + (size_t)wrow * D)
                             : (outB + (size_t)(wrow - nA) * D);
    if (FIRST) {
        if (half == 0) {
            __half2 h0 = __floats2half2_rn(a.x, a.y);
            __half2 h1 = __floats2half2_rn(a.z, a.w);
            uint2 packed;
            packed.x = *(const unsigned int*)&h0;
            packed.y = *(const unsigned int*)&h1;
            *((uint2*)(fnext + (size_t)(rbase + wrow) * D) + chunk) = packed;
        } else {
            uint2 r = *((const uint2*)(fb + (size_t)wrow * D) + chunk);
            float2 fa = __half22float2(*(__half2*)&r.x);
            float2 fbv = __half22float2(*(__half2*)&r.y);
            *((float4*)dst + chunk) = make_float4(
                fa.x * k + a.x * scale, fa.y * k + a.y * scale,
                fbv.x * k + a.z * scale, fbv.y * k + a.w * scale);
        }
    } else {
        if (half == 0) {
            float4* d = (float4*)dst + chunk;
            float4 o = *d;
            o.x += a.x * scale; o.y += a.y * scale;
            o.z += a.z * scale; o.w += a.w * scale;
            *d = o;
        }
    }
}

// ---- persistent streams/events ----
static cudaStream_t s_strm[3];
static cudaEvent_t s_root, s_init, s_done[3];
static bool s_ready = false;

extern "C" void kernel_launch(void* const* d_in, const int* in_sizes, int n_in,
                              void* d_out, int out_size) {
    const float* users_feature   = (const float*)d_in[0];
    const float* items_feature   = (const float*)d_in[1];
    const float* bundles_feature = (const float*)d_in[2];
    const float* vals_[3] = {(const float*)d_in[3], (const float*)d_in[4], (const float*)d_in[5]};
    const int* rows_[3] = {(const int*)d_in[6], (const int*)d_in[8], (const int*)d_in[10]};
    const int* cols_[3] = {(const int*)d_in[7], (const int*)d_in[9], (const int*)d_in[11]};

    int U  = in_sizes[0] / D;
    int NI = in_sizes[1] / D;
    int NB = in_sizes[2] / D;
    int nnz_[3] = {in_sizes[3], in_sizes[4], in_sizes[5]};   // UI, BI, UB

    int R1 = U + NI;
    int R2 = R1 + NB + NI;
    int ntot = R2 + U + NB;

    if (!s_ready) {
        for (int g = 0; g < 3; g++) {
            cudaStreamCreateWithFlags(&s_strm[g], cudaStreamNonBlocking);
            cudaEventCreateWithFlags(&s_done[g], cudaEventDisableTiming);
        }
        cudaEventCreateWithFlags(&s_root, cudaEventDisableTiming);
        cudaEventCreateWithFlags(&s_init, cudaEventDisableTiming);
        s_ready = true;
    }

    float* out = (float*)d_out;
    __half *f0, *f1;
    float2* edges;
    int *counts, *offs, *cursor;
    unsigned long long* desc;
    unsigned int* ticket;
    cudaGetSymbolAddress((void**)&f0, g_f0);
    cudaGetSymbolAddress((void**)&f1, g_f1);
    cudaGetSymbolAddress((void**)&edges, g_edges);
    cudaGetSymbolAddress((void**)&counts, g_counts);
    cudaGetSymbolAddress((void**)&offs, g_offs);
    cudaGetSymbolAddress((void**)&cursor, g_cursor);
    cudaGetSymbolAddress((void**)&desc, g_desc);
    cudaGetSymbolAddress((void**)&ticket, g_ticket);

    // Output layout: [UI_u(U), UB_u(U), BI_b(NB), UB_b(NB), UI_i(NI), BI_i(NI)]
    float* o_ui_u = out;
    float* o_ub_u = out + (size_t)U * D;
    float* o_bi_b = out + (size_t)2 * U * D;
    float* o_ub_b = out + ((size_t)2 * U + NB) * D;
    float* o_ui_i = out + ((size_t)2 * U + 2 * NB) * D;
    float* o_bi_i = out + ((size_t)2 * U + 2 * NB + NI) * D;

    struct G { int rbase, n, nA, ebase; float *oA, *oB; };
    G gs[3] = {
        {0,  U + NI,  U,  0,                   o_ui_u, o_ui_i},
        {R1, NB + NI, NB, nnz_[0],             o_bi_b, o_bi_i},
        {R2, U + NB,  U,  nnz_[0] + nnz_[1],   o_ub_u, o_ub_b},
    };

    cudaEventRecord(s_root, 0);
    init_kernel<<<(ntot * (D / 4) + 255) / 256, 256>>>(
        users_feature, items_feature, bundles_feature, U, NB, R1, R2, ntot, f0);
    cudaEventRecord(s_init, 0);

    for (int g = 0; g < 3; g++) {
        cudaStream_t st = s_strm[g];
        const G& G_ = gs[g];
        int n = G_.n;
        int nb = (n + SCAN_B - 1) / SCAN_B;
        int* cnt = counts + G_.rbase;
        int* off = offs + G_.rbase + g;        // +g pad avoids boundary overlap
        int* cur = cursor + G_.rbase;
        float2* edg = edges + G_.ebase;
        unsigned long long* dsc = desc + (size_t)g * MAXBLKS;
        unsigned int* tkt = ticket + g;

        cudaStreamWaitEvent(st, s_root, 0);
        cudaMemsetAsync(cnt, 0, (size_t)n * sizeof(int), st);
        cudaMemsetAsync(dsc, 0, (size_t)nb * sizeof(unsigned long long), st);
        cudaMemsetAsync(tkt, 0, sizeof(unsigned int), st);

        int eth = (nnz_[g] + 7) / 8;
        hist_kernel<<<(eth + 255) / 256, 256, 0, st>>>(rows_[g], nnz_[g], cnt);
        scan_kernel<<<nb, SCAN_B, 0, st>>>(cnt, n, off, cur, dsc, tkt);
        bucket_kernel<<<(eth + 255) / 256, 256, 0, st>>>(rows_[g], cols_[g], vals_[g],
                                                         nnz_[g], cur, edg);

        cudaStreamWaitEvent(st, s_init, 0);
        int blocks = (n + 7) / 8;
        spmm_kernel<true><<<blocks, 256, 0, st>>>(edg, off, f0, f1,
                                                  G_.rbase, n, G_.nA, G_.oA, G_.oB);
        spmm_kernel<false><<<blocks, 256, 0, st>>>(edg, off, f1, nullptr,
                                                   G_.rbase, n, G_.nA, G_.oA, G_.oB);
        cudaEventRecord(s_done[g], st);
    }

    for (int g = 0; g < 3; g++)
        cudaStreamWaitEvent(0, s_done[g], 0);
}